// round 1
// baseline (speedup 1.0000x reference)
#include <cuda_runtime.h>
#include <math.h>

// DINAttenLayer: B=2048, T=200, E=64, MLP 256->80->40->1 (sigmoid), masked softmax,
// attention-weighted sum of facts.
//
// Key algebraic fold: din = [q, f, q-f, q*f] concat =>
//   z1 = f @ M_b + qW_b   with  M_b = (W1[64:128] - W1[128:192]) + diag(q) @ W1[192:256]
//                               qW_b = q @ (W1[0:64] + W1[128:192]) + b1
// => 64x80 GEMV per (b,t) instead of 256x80 (2.45x FLOP reduction).

#define T_DIN   200
#define E_DIN   64
#define H1_DIN  80
#define H2_DIN  40
#define NTHREADS 256
#define M_PITCH 68          // padded row pitch (floats) for Msh: 272B = 17*16B, float4-aligned

__global__ __launch_bounds__(NTHREADS)
void din_atten_kernel(const float* __restrict__ query,   // (B,64)
                      const float* __restrict__ facts,   // (B,200,64)
                      const int*   __restrict__ mask,    // (B,200)
                      const float* __restrict__ W1,      // (256,80) row-major
                      const float* __restrict__ b1,      // (80)
                      const float* __restrict__ W2,      // (80,40)
                      const float* __restrict__ b2,      // (40)
                      const float* __restrict__ W3,      // (40,1)
                      const float* __restrict__ b3,      // (1)
                      float* __restrict__ out)           // (B,64)
{
    const int b   = blockIdx.x;
    const int tid = threadIdx.x;

    __shared__ float Msh[H1_DIN][M_PITCH];   // M^T: Msh[h][d]
    __shared__ float W2sh[H2_DIN][H1_DIN];   // W2^T: W2sh[k][h]
    __shared__ float qWsh[H1_DIN];
    __shared__ float W3sh[H2_DIN];
    __shared__ float b2sh[H2_DIN];
    __shared__ float qsh[E_DIN];
    __shared__ float scores[T_DIN];
    __shared__ float red[8];
    __shared__ float s_b3;
    __shared__ float s_inv;
    __shared__ float wsum[4][E_DIN];

    // ---- stage q + small weights ----
    if (tid < E_DIN)                       qsh[tid]        = query[(size_t)b * E_DIN + tid];
    if (tid >= 64 && tid < 64 + H2_DIN)    W3sh[tid - 64]  = W3[tid - 64];
    if (tid >= 128 && tid < 128 + H2_DIN)  b2sh[tid - 128] = b2[tid - 128];
    if (tid == 192)                        s_b3            = b3[0];
    __syncthreads();

    // ---- build per-batch folded layer-1 matrix M_b (transposed) ----
    // i -> (d = i/80, h = i%80): W1 reads are coalesced over h (stride-1), L2-resident.
    for (int i = tid; i < E_DIN * H1_DIN; i += NTHREADS) {
        int d = i / H1_DIN;
        int h = i - d * H1_DIN;
        float wb = W1[(64  + d) * H1_DIN + h];
        float wc = W1[(128 + d) * H1_DIN + h];
        float wd = W1[(192 + d) * H1_DIN + h];
        Msh[h][d] = (wb - wc) + qsh[d] * wd;
    }
    // qW_b[h] = b1[h] + sum_d q[d]*(W1a[d][h] + W1c[d][h])
    if (tid < H1_DIN) {
        float s = b1[tid];
        #pragma unroll 8
        for (int d = 0; d < E_DIN; ++d)
            s += qsh[d] * (W1[d * H1_DIN + tid] + W1[(128 + d) * H1_DIN + tid]);
        qWsh[tid] = s;
    }
    // W2 transposed: i -> (k = i%40, h = i/40): global reads fully coalesced.
    for (int i = tid; i < H1_DIN * H2_DIN; i += NTHREADS) {
        int h = i / H2_DIN;
        int k = i - h * H2_DIN;
        W2sh[k][h] = W2[h * H2_DIN + k];
    }
    __syncthreads();

    // ---- per-t MLP: thread t handles one history position ----
    const int t = tid;
    if (t < T_DIN) {
        const float4* fp = (const float4*)(facts + ((size_t)b * T_DIN + t) * E_DIN);
        float f[E_DIN];
        #pragma unroll
        for (int i = 0; i < E_DIN / 4; ++i) {
            float4 v = fp[i];
            f[4*i+0] = v.x; f[4*i+1] = v.y; f[4*i+2] = v.z; f[4*i+3] = v.w;
        }

        // layer 1: h1 = sigmoid(f @ M + qW)   (broadcast LDS.128 of M rows)
        float h1[H1_DIN];
        for (int h = 0; h < H1_DIN; ++h) {
            const float4* mrow = (const float4*)&Msh[h][0];
            float a0 = 0.f, a1 = 0.f, a2 = 0.f, a3 = 0.f;
            #pragma unroll
            for (int i = 0; i < E_DIN / 4; ++i) {
                float4 m = mrow[i];
                a0 += f[4*i+0] * m.x;
                a1 += f[4*i+1] * m.y;
                a2 += f[4*i+2] * m.z;
                a3 += f[4*i+3] * m.w;
            }
            float z = qWsh[h] + ((a0 + a1) + (a2 + a3));
            h1[h] = 1.f / (1.f + __expf(-z));
        }

        // layer 2: h2 = sigmoid(h1 @ W2)
        float h2[H2_DIN];
        for (int k = 0; k < H2_DIN; ++k) {
            const float4* wrow = (const float4*)&W2sh[k][0];
            float a0 = 0.f, a1 = 0.f, a2 = 0.f, a3 = 0.f;
            #pragma unroll
            for (int i = 0; i < H1_DIN / 4; ++i) {
                float4 w = wrow[i];
                a0 += h1[4*i+0] * w.x;
                a1 += h1[4*i+1] * w.y;
                a2 += h1[4*i+2] * w.z;
                a3 += h1[4*i+3] * w.w;
            }
            float z = b2sh[k] + ((a0 + a1) + (a2 + a3));
            h2[k] = 1.f / (1.f + __expf(-z));
        }

        // layer 3: score
        float s = s_b3;
        #pragma unroll
        for (int k = 0; k < H2_DIN; ++k) s += h2[k] * W3sh[k];

        // mask: PAD = -2^32+1 (exp underflows to exactly 0 after max-subtraction)
        int mk = mask[(size_t)b * T_DIN + t];
        scores[t] = (mk == 1) ? s : -4294967295.0f;
    }
    __syncthreads();

    // ---- masked softmax over T=200 ----
    const int lane = tid & 31, wid = tid >> 5;
    float v = (tid < T_DIN) ? scores[tid] : -INFINITY;
    #pragma unroll
    for (int off = 16; off > 0; off >>= 1)
        v = fmaxf(v, __shfl_xor_sync(0xffffffffu, v, off));
    if (lane == 0) red[wid] = v;
    __syncthreads();
    if (tid == 0) {
        float m = red[0];
        #pragma unroll
        for (int i = 1; i < 8; ++i) m = fmaxf(m, red[i]);
        red[0] = m;
    }
    __syncthreads();
    const float mx = red[0];

    float e = (tid < T_DIN) ? __expf(scores[tid] - mx) : 0.f;
    if (tid < T_DIN) scores[tid] = e;     // unnormalized weight
    __syncthreads();                      // scores stable before sum-reduce reuses red[]
    float sv = e;
    #pragma unroll
    for (int off = 16; off > 0; off >>= 1)
        sv += __shfl_xor_sync(0xffffffffu, sv, off);
    if (lane == 0) red[wid] = sv;
    __syncthreads();
    if (tid == 0) {
        float s = 0.f;
        #pragma unroll
        for (int i = 0; i < 8; ++i) s += red[i];
        s_inv = 1.f / s;
    }
    __syncthreads();

    // ---- weighted sum: out[b][e] = (1/S) * sum_t e[t] * facts[b][t][e] ----
    {
        const int e_idx  = tid & 63;
        const int chunk  = tid >> 6;                 // 0..3, 50 t's each
        const float* fb  = facts + (size_t)b * T_DIN * E_DIN;
        float acc = 0.f;
        const int t0 = chunk * 50;
        #pragma unroll 5
        for (int tt = t0; tt < t0 + 50; ++tt)
            acc += scores[tt] * fb[tt * E_DIN + e_idx];   // coalesced, L2-hot
        wsum[chunk][e_idx] = acc;
    }
    __syncthreads();
    if (tid < E_DIN)
        out[(size_t)b * E_DIN + tid] =
            (wsum[0][tid] + wsum[1][tid] + wsum[2][tid] + wsum[3][tid]) * s_inv;
}

extern "C" void kernel_launch(void* const* d_in, const int* in_sizes, int n_in,
                              void* d_out, int out_size)
{
    const float* query = (const float*)d_in[0];
    const float* facts = (const float*)d_in[1];
    const int*   mask  = (const int*)  d_in[2];
    const float* W1    = (const float*)d_in[3];
    const float* b1    = (const float*)d_in[4];
    const float* W2    = (const float*)d_in[5];
    const float* b2    = (const float*)d_in[6];
    const float* W3    = (const float*)d_in[7];
    const float* b3    = (const float*)d_in[8];
    float* out = (float*)d_out;

    const int B = in_sizes[0] / E_DIN;   // 2048
    din_atten_kernel<<<B, NTHREADS>>>(query, facts, mask, W1, b1, W2, b2, W3, b3, out);
}

// round 2
// speedup vs baseline: 1.4511x; 1.4511x over previous
#include <cuda_runtime.h>
#include <math.h>

// DIN attention, compacted + warp-tiled.
// Fold: z1 = f@M_b + qW_b, M_b[d][h] = W1[64+d][h] - W1[128+d][h] + q[d]*W1[192+d][h]
//       qW_b[h] = b1[h] + sum_d q[d]*(W1[d][h] + W1[128+d][h])

#define TT   200
#define EE   64
#define H1   80
#define H2   40
#define NT   256
#define PF   132    // Fsh pitch (cols): 128 cap + pad; 132%32=4 -> 4-way store conflicts only
#define PH   203    // Hsh pitch: odd -> conflict-free strided stores/reads
#define PM   96     // Msh/qW padded width (zeros in 80..95)
#define FCAP 128    // compacted t's staged in smem

__device__ __forceinline__ float sigm(float z) { return 1.0f / (1.0f + __expf(-z)); }

__global__ __launch_bounds__(NT, 2)
void din_atten_kernel(const float* __restrict__ query,   // (B,64)
                      const float* __restrict__ facts,   // (B,200,64)
                      const int*   __restrict__ mask,    // (B,200)
                      const float* __restrict__ W1,      // (256,80)
                      const float* __restrict__ b1,      // (80)
                      const float* __restrict__ W2,      // (80,40)
                      const float* __restrict__ b2,      // (40)
                      const float* __restrict__ W3,      // (40,1)
                      const float* __restrict__ b3,      // (1)
                      float* __restrict__ out)           // (B,64)
{
    extern __shared__ float dsm[];
    float* Hsh = dsm;                    // 80*203 = 16240 floats (h-major: Hsh[h*PH + t])
    float* Fsh = dsm;                    // union: 64*132 = 8448 floats (k-major: Fsh[d*PF + j])
    float* Msh = dsm + H1 * PH;          // 64*96  (k-major: Msh[d*PM + h], cols 80..95 = 0)
    float* W2s = Msh + EE * PM;          // 80*40  (h-major rows, same layout as W2)
    float* qWs = W2s + H1 * H2;          // 96 (80 + zero pad)
    float* qsh = qWs + PM;               // 64
    float* W3s = qsh + EE;               // 40
    float* b2s = W3s + H2;               // 40

    __shared__ float scores[TT];
    __shared__ int   tact[TT];
    __shared__ int   wcnt[8];
    __shared__ float red[8];
    __shared__ int   nact_sh;
    __shared__ float s_b3, s_inv;
    __shared__ float wsum[4][EE];

    const int b    = blockIdx.x;
    const int tid  = threadIdx.x;
    const int lane = tid & 31;
    const int wid  = tid >> 5;
    const float* fb = facts + (size_t)b * TT * EE;

    // ---- stage q + tiny weights ----
    if (tid < EE)              qsh[tid]            = query[(size_t)b * EE + tid];
    else if (tid < EE + H2)    W3s[tid - EE]       = W3[tid - EE];
    else if (tid < EE + 2*H2)  b2s[tid - EE - H2]  = b2[tid - EE - H2];
    else if (tid == EE + 2*H2) s_b3                = b3[0];

    // ---- deterministic mask compaction ----
    bool act = (tid < TT) && (mask[(size_t)b * TT + tid] == 1);
    unsigned ball = __ballot_sync(0xffffffffu, act);
    if (lane == 0) wcnt[wid] = __popc(ball);
    __syncthreads();
    if (tid == 0) {
        int s = 0;
        #pragma unroll
        for (int w = 0; w < 8; ++w) { int c = wcnt[w]; wcnt[w] = s; s += c; }
        nact_sh = s;
    }
    __syncthreads();
    if (act) tact[wcnt[wid] + __popc(ball & ((1u << lane) - 1u))] = tid;
    __syncthreads();
    const int  nact0 = nact_sh;
    const bool uni   = (nact0 == 0);          // all masked -> uniform softmax
    const int  nact  = uni ? TT : nact0;

    if (uni) {
        if (tid < TT) { tact[tid] = tid; scores[tid] = 0.0f; }
    } else {
        // ---- build M (k-major, padded), qW, W2 copy ----
        for (int i = tid; i < EE * PM; i += NT) {
            int d = i / PM, h = i - d * PM;
            float v = 0.0f;
            if (h < H1)
                v = (W1[(EE + d) * H1 + h] - W1[(2*EE + d) * H1 + h])
                    + qsh[d] * W1[(3*EE + d) * H1 + h];
            Msh[i] = v;
        }
        if (tid < PM) {
            float s = 0.0f;
            if (tid < H1) {
                s = b1[tid];
                for (int d = 0; d < EE; ++d)
                    s += qsh[d] * (W1[d * H1 + tid] + W1[(2*EE + d) * H1 + tid]);
            }
            qWs[tid] = s;
        }
        for (int i = tid; i < H1 * H2; i += NT) W2s[i] = W2[i];

        // ---- stage F k-major (transposed, compacted; first FCAP only) ----
        const int nst = (nact0 < FCAP) ? nact0 : FCAP;
        for (int i = tid; i < EE * nst; i += NT) {
            int d = i & 63, j = i >> 6;                       // lanes: consecutive d -> coalesced LDG
            Fsh[d * PF + j] = fb[(size_t)tact[j] * EE + d];   // 4-way STS conflict, one-time
        }
        __syncthreads();

        // ---- layer 1: warp computes 16t x 80h tile, acc in regs ----
        const int tb = wid << 4;
        float acc[16][3];
        #pragma unroll
        for (int i = 0; i < 16; ++i) { acc[i][0] = 0.f; acc[i][1] = 0.f; acc[i][2] = 0.f; }

        if (tb < nst) {
            #pragma unroll 4
            for (int d = 0; d < EE; ++d) {
                const float4* fr = (const float4*)&Fsh[d * PF + tb];   // warp-uniform
                float4 fa = fr[0], fbv = fr[1], fc = fr[2], fd4 = fr[3];
                float fv[16] = { fa.x, fa.y, fa.z, fa.w,  fbv.x, fbv.y, fbv.z, fbv.w,
                                 fc.x, fc.y, fc.z, fc.w,  fd4.x, fd4.y, fd4.z, fd4.w };
                float m0 = Msh[d * PM + lane];
                float m1 = Msh[d * PM + lane + 32];
                float m2 = Msh[d * PM + lane + 64];   // zero-padded for lane>=16
                #pragma unroll
                for (int i = 0; i < 16; ++i) {
                    acc[i][0] += fv[i] * m0;
                    acc[i][1] += fv[i] * m1;
                    acc[i][2] += fv[i] * m2;
                }
            }
        }
        __syncthreads();   // ALL Fsh reads done -> Hsh may overwrite union

        if (tb < nst) {
            #pragma unroll
            for (int i = 0; i < 16; ++i) {
                int t = tb + i;
                #pragma unroll
                for (int j3 = 0; j3 < 3; ++j3) {
                    int h = lane + 32 * j3;
                    if (h < H1) Hsh[h * PH + t] = sigm(acc[i][j3] + qWs[h]);  // conflict-free (odd pitch)
                }
            }
        }

        // ---- rare overflow (nact0 > 128): recompute from global (uniform LDG) ----
        if (nact0 > FCAP) {
            int tiles2 = (nact0 - FCAP + 15) >> 4;
            if (wid < tiles2) {
                int tb2 = FCAP + (wid << 4);
                int gt[16];
                #pragma unroll
                for (int i = 0; i < 16; ++i) {
                    int jj = tb2 + i; if (jj > nact0 - 1) jj = nact0 - 1;
                    gt[i] = tact[jj];
                }
                float a2[16][3];
                #pragma unroll
                for (int i = 0; i < 16; ++i) { a2[i][0] = 0.f; a2[i][1] = 0.f; a2[i][2] = 0.f; }
                for (int d = 0; d < EE; ++d) {
                    float m0 = Msh[d * PM + lane];
                    float m1 = Msh[d * PM + lane + 32];
                    float m2 = Msh[d * PM + lane + 64];
                    #pragma unroll
                    for (int i = 0; i < 16; ++i) {
                        float fv = fb[(size_t)gt[i] * EE + d];
                        a2[i][0] += fv * m0; a2[i][1] += fv * m1; a2[i][2] += fv * m2;
                    }
                }
                #pragma unroll
                for (int i = 0; i < 16; ++i) {
                    int t = tb2 + i;
                    if (t < nact0) {
                        #pragma unroll
                        for (int j3 = 0; j3 < 3; ++j3) {
                            int h = lane + 32 * j3;
                            if (h < H1) Hsh[h * PH + t] = sigm(a2[i][j3] + qWs[h]);
                        }
                    }
                }
            }
        }
        __syncthreads();

        // ---- layers 2+3: one compacted t per thread ----
        if (tid < nact0) {
            float z2[H2];
            #pragma unroll
            for (int k = 0; k < H2; ++k) z2[k] = b2s[k];
            #pragma unroll 2
            for (int h = 0; h < H1; ++h) {
                float hv = Hsh[h * PH + tid];                 // conflict-free
                const float4* wr = (const float4*)&W2s[h * H2];  // warp-uniform broadcast
                #pragma unroll
                for (int k4 = 0; k4 < H2 / 4; ++k4) {
                    float4 w = wr[k4];
                    z2[4*k4+0] += hv * w.x;  z2[4*k4+1] += hv * w.y;
                    z2[4*k4+2] += hv * w.z;  z2[4*k4+3] += hv * w.w;
                }
            }
            float sc = s_b3;
            #pragma unroll
            for (int k = 0; k < H2; ++k) sc += sigm(z2[k]) * W3s[k];
            scores[tid] = sc;
        }
    }
    __syncthreads();

    // ---- softmax over compacted scores (uniform mode: all zeros over 200) ----
    float v = (tid < nact) ? scores[tid] : -INFINITY;
    #pragma unroll
    for (int off = 16; off > 0; off >>= 1)
        v = fmaxf(v, __shfl_xor_sync(0xffffffffu, v, off));
    if (lane == 0) red[wid] = v;
    __syncthreads();
    if (tid == 0) {
        float m = red[0];
        #pragma unroll
        for (int i = 1; i < 8; ++i) m = fmaxf(m, red[i]);
        red[0] = m;
    }
    __syncthreads();
    const float mx = red[0];

    float e = (tid < nact) ? __expf(scores[tid] - mx) : 0.0f;
    if (tid < nact) scores[tid] = e;
    __syncthreads();
    float sv = e;
    #pragma unroll
    for (int off = 16; off > 0; off >>= 1)
        sv += __shfl_xor_sync(0xffffffffu, sv, off);
    if (lane == 0) red[wid] = sv;
    __syncthreads();
    if (tid == 0) {
        float s = 0.0f;
        #pragma unroll
        for (int i = 0; i < 8; ++i) s += red[i];
        s_inv = 1.0f / s;
    }
    __syncthreads();

    // ---- weighted sum over active t (global re-read, L2-hot, coalesced) ----
    {
        const int ei = tid & 63, ch = tid >> 6;
        float a = 0.0f;
        for (int j = ch; j < nact; j += 4)
            a += scores[j] * fb[(size_t)tact[j] * EE + ei];
        wsum[ch][ei] = a;
    }
    __syncthreads();
    if (tid < EE)
        out[(size_t)b * EE + tid] =
            (wsum[0][tid] + wsum[1][tid] + wsum[2][tid] + wsum[3][tid]) * s_inv;
}

#define DSM_BYTES ((H1*PH + EE*PM + H1*H2 + PM + EE + H2 + H2) * (int)sizeof(float))

extern "C" void kernel_launch(void* const* d_in, const int* in_sizes, int n_in,
                              void* d_out, int out_size)
{
    const float* query = (const float*)d_in[0];
    const float* facts = (const float*)d_in[1];
    const int*   mask  = (const int*)  d_in[2];
    const float* W1    = (const float*)d_in[3];
    const float* b1    = (const float*)d_in[4];
    const float* W2    = (const float*)d_in[5];
    const float* b2    = (const float*)d_in[6];
    const float* W3    = (const float*)d_in[7];
    const float* b3    = (const float*)d_in[8];
    float* out = (float*)d_out;

    cudaFuncSetAttribute(din_atten_kernel,
                         cudaFuncAttributeMaxDynamicSharedMemorySize, DSM_BYTES);

    const int B = in_sizes[0] / EE;   // 2048
    din_atten_kernel<<<B, NT, DSM_BYTES>>>(query, facts, mask, W1, b1, W2, b2, W3, b3, out);
}